// round 10
// baseline (speedup 1.0000x reference)
#include <cuda_runtime.h>
#include <cuda_bf16.h>
#include <math.h>
#include <stdint.h>

#define BB 2048
#define SS 200
#define DD 192
#define H1 64
#define H2 32
#define NT 256
#define SPAD 208

typedef unsigned long long ull;

// ---- smem layout (float idx) ----
#define SM_AB 0                        // two A bufs: 2 * 64row * 768B = 98304 B = 24576 f (Ht overlay after GEMM)
#define SM_B  24576                    // B [64][384] bf16 = 49152 B = 12288 f
#define SM_QS 36864                    // 192
#define SM_B1 (SM_QS + 192)            // 64
#define SM_W2 (SM_B1 + 64)             // 2048
#define SM_W3 (SM_W2 + 2048)           // 32
#define SM_B2 (SM_W3 + 32)             // 32
#define SM_SC (SM_B2 + 32)             // 256
#define SM_WGT (SM_SC + 256)           // 256
#define SM_RED (SM_WGT + 256)          // 64
#define SMEM_FLOATS (SM_RED + 64)      // 39808 f = 159232 B

#define ABUF_BYTES 49152

static __device__ __forceinline__ ull pk2(float x) {
    ull r; asm("mov.b64 %0, {%1, %1};" : "=l"(r) : "f"(x)); return r;
}
static __device__ __forceinline__ void fma2(ull& d, ull a, ull b) {
    asm("fma.rn.f32x2 %0, %1, %2, %0;" : "+l"(d) : "l"(a), "l"(b));
}
static __device__ __forceinline__ float2 up2(ull v) {
    float2 r; asm("mov.b64 {%0, %1}, %2;" : "=f"(r.x), "=f"(r.y) : "l"(v)); return r;
}

#define LDSM4(r0, r1, r2, r3, addr) \
    asm volatile("ldmatrix.sync.aligned.m8n8.x4.shared.b16 {%0,%1,%2,%3}, [%4];" \
                 : "=r"(r0), "=r"(r1), "=r"(r2), "=r"(r3) : "r"(addr))

#define MMA16816(d0, d1, d2, d3, a0, a1, a2, a3, b0, b1) \
    asm volatile("mma.sync.aligned.m16n8k16.row.col.f32.bf16.bf16.f32 " \
                 "{%0,%1,%2,%3},{%4,%5,%6,%7},{%8,%9},{%0,%1,%2,%3};" \
                 : "+f"(d0), "+f"(d1), "+f"(d2), "+f"(d3) \
                 : "r"(a0), "r"(a1), "r"(a2), "r"(a3), "r"(b0), "r"(b1))

// Convert one 64-row A tile (keys rows [row0,row0+nrows)) to bf16 hi/lo, swizzled.
static __device__ __forceinline__ void conv_tile(char* abuf, const float* kbase, int row0, int nrows, int tid) {
    int total = nrows * 48;            // float4 units
    for (int f = tid; f < total; f += NT) {
        int r = f / 48;
        int q = f - r * 48;
        int grow = row0 + r;
        float4 kv = make_float4(0.f, 0.f, 0.f, 0.f);
        if (grow < SS)
            kv = *reinterpret_cast<const float4*>(kbase + (size_t)grow * DD + 4 * q);
        __nv_bfloat162 h01 = __floats2bfloat162_rn(kv.x, kv.y);
        __nv_bfloat162 h23 = __floats2bfloat162_rn(kv.z, kv.w);
        __nv_bfloat162 l01 = __floats2bfloat162_rn(kv.x - __bfloat162float(h01.x),
                                                   kv.y - __bfloat162float(h01.y));
        __nv_bfloat162 l23 = __floats2bfloat162_rn(kv.z - __bfloat162float(h23.x),
                                                   kv.w - __bfloat162float(h23.y));
        uint32_t x   = (uint32_t)(r & 7) << 4;
        uint32_t rb  = (uint32_t)r * 768u;
        uint32_t cbh = ((uint32_t)(8 * q)) ^ x;          // hi bytes
        uint32_t cbl = ((uint32_t)(384 + 8 * q)) ^ x;    // lo bytes
        uint2 hv, lv;
        hv.x = *reinterpret_cast<uint32_t*>(&h01);
        hv.y = *reinterpret_cast<uint32_t*>(&h23);
        lv.x = *reinterpret_cast<uint32_t*>(&l01);
        lv.y = *reinterpret_cast<uint32_t*>(&l23);
        *reinterpret_cast<uint2*>(abuf + rb + cbh) = hv;
        *reinterpret_cast<uint2*>(abuf + rb + cbl) = lv;
    }
}

__global__ __launch_bounds__(NT)
void rich_attn_kernel(const float* __restrict__ query,
                      const float* __restrict__ keys,
                      const int*   __restrict__ kmask,
                      const float* __restrict__ W1,
                      const float* __restrict__ b1,
                      const float* __restrict__ a1p,
                      const float* __restrict__ W2,
                      const float* __restrict__ b2,
                      const float* __restrict__ a2p,
                      const float* __restrict__ W3,
                      const float* __restrict__ b3p,
                      float* __restrict__ out)
{
    extern __shared__ float sm[];
    const int tid = threadIdx.x;
    const int wid = tid >> 5;
    const int lid = tid & 31;
    const int b   = blockIdx.x;

    const float a1 = a1p[0];
    const float a2 = a2p[0];
    const float b3 = b3p[0];

    const float* kbase = keys + (size_t)b * SS * DD;
    char* abufs = reinterpret_cast<char*>(sm + SM_AB);
    char* smB   = reinterpret_cast<char*>(sm + SM_B);
    const uint32_t base_u32 = (uint32_t)__cvta_generic_to_shared((void*)sm);
    const uint32_t abase_u32 = base_u32;                 // SM_AB = 0
    const uint32_t bbase_u32 = base_u32 + SM_B * 4;

    float* qs    = sm + SM_QS;
    float* bias1 = sm + SM_B1;
    float* w2s   = sm + SM_W2;
    float* w3s   = sm + SM_W3;
    float* b2s   = sm + SM_B2;
    float* score = sm + SM_SC;
    float* wgt   = sm + SM_WGT;
    float* red   = sm + SM_RED;

    // ---- small loads ----
    if (tid < DD) qs[tid] = query[(size_t)b * DD + tid];
    for (int idx = tid; idx < H1 * H2; idx += NT) w2s[idx] = W2[idx];
    if (tid < H2) { w3s[tid] = W3[tid]; b2s[tid] = b2[tid]; }
    if (tid >= SS) score[tid] = -INFINITY;
    __syncthreads();   // qs ready

    // ---- B = weffT hi/lo, swizzled [h][384] ----
    for (int idx = tid; idx < DD * H1; idx += NT) {
        int k = idx >> 6;
        int h = idx & 63;
        float v = W1[idx] + W1[(size_t)(576 + k) * H1 + h] + qs[k] * W1[(size_t)(384 + k) * H1 + h];
        __nv_bfloat16 hb = __float2bfloat16_rn(v);
        __nv_bfloat16 lb = __float2bfloat16_rn(v - __bfloat162float(hb));
        uint32_t x  = (uint32_t)(h & 7) << 4;
        uint32_t rb = (uint32_t)h * 768u;
        *reinterpret_cast<__nv_bfloat16*>(smB + rb + (((uint32_t)(2 * k)) ^ x))       = hb;
        *reinterpret_cast<__nv_bfloat16*>(smB + rb + (((uint32_t)(384 + 2 * k)) ^ x)) = lb;
    }
    // ---- bias1 partials (wgt scratch) ----
    {
        int h = tid & 63;
        int c = tid >> 6;
        float acc_ = 0.f;
        int i0 = c * 48;
        #pragma unroll 4
        for (int i = i0; i < i0 + 48; i++)
            acc_ = fmaf(qs[i], W1[(size_t)(192 + i) * H1 + h] - W1[(size_t)(576 + i) * H1 + h], acc_);
        wgt[tid] = acc_;
    }
    // ---- conv pass 0 -> buf0 ----
    conv_tile(abufs, kbase, 0, 64, tid);
    __syncthreads();
    if (tid < H1)
        bias1[tid] = b1[tid] + wgt[tid] + wgt[tid + 64] + wgt[tid + 128] + wgt[tid + 192];

    // ---- GEMM passes ----
    float c0[4][16];        // [pass][4 n8-tiles * 4]
    #pragma unroll
    for (int p = 0; p < 4; p++)
        #pragma unroll
        for (int j = 0; j < 16; j++) c0[p][j] = 0.f;

    // lane-invariant ldsm address pieces
    const uint32_t uA = ((uint32_t)(lid >> 4)) * 16u;
    const uint32_t jB = (uint32_t)(lid >> 3);
    const uint32_t uB = (jB & 1u) * 16u;
    const uint32_t xb = ((uint32_t)(lid & 7)) << 4;

    for (int p = 0; p < 4; p++) {
        const bool active = (p < 3) || (wid < 2);
        if (active) {
            const int mt = (p < 3) ? (wid >> 1) : 0;
            const int nb = (p < 3) ? ((wid & 1) * 32) : (wid * 32);
            const uint32_t rowA = (uint32_t)(mt * 16 + (lid & 15));
            const uint32_t xa = (rowA & 7u) << 4;
            const uint32_t aB = abase_u32 + (uint32_t)(p & 1) * ABUF_BYTES + rowA * 768u;
            const uint32_t rowB0 = (uint32_t)nb + (jB >> 1) * 8u + (uint32_t)(lid & 7);
            const uint32_t bB0 = bbase_u32 + rowB0 * 768u;
            const uint32_t bB1 = bB0 + 16u * 768u;
            float* cc = c0[p];

            #pragma unroll
            for (int ks = 0; ks < 12; ks++) {
                uint32_t kh = (uint32_t)(ks * 32);
                uint32_t kl = kh + 384u;
                uint32_t ah0, ah1, ah2, ah3, al0, al1, al2, al3;
                LDSM4(ah0, ah1, ah2, ah3, aB + ((kh + uA) ^ xa));
                LDSM4(al0, al1, al2, al3, aB + ((kl + uA) ^ xa));
                uint32_t bh00, bh01, bh10, bh11, bh20, bh21, bh30, bh31;
                LDSM4(bh00, bh01, bh10, bh11, bB0 + ((kh + uB) ^ xb));
                LDSM4(bh20, bh21, bh30, bh31, bB1 + ((kh + uB) ^ xb));
                uint32_t bl00, bl01, bl10, bl11, bl20, bl21, bl30, bl31;
                LDSM4(bl00, bl01, bl10, bl11, bB0 + ((kl + uB) ^ xb));
                LDSM4(bl20, bl21, bl30, bl31, bB1 + ((kl + uB) ^ xb));

                // t0: Ah*Bh
                MMA16816(cc[0], cc[1], cc[2], cc[3],     ah0, ah1, ah2, ah3, bh00, bh01);
                MMA16816(cc[4], cc[5], cc[6], cc[7],     ah0, ah1, ah2, ah3, bh10, bh11);
                MMA16816(cc[8], cc[9], cc[10], cc[11],   ah0, ah1, ah2, ah3, bh20, bh21);
                MMA16816(cc[12], cc[13], cc[14], cc[15], ah0, ah1, ah2, ah3, bh30, bh31);
                // t1: Al*Bh
                MMA16816(cc[0], cc[1], cc[2], cc[3],     al0, al1, al2, al3, bh00, bh01);
                MMA16816(cc[4], cc[5], cc[6], cc[7],     al0, al1, al2, al3, bh10, bh11);
                MMA16816(cc[8], cc[9], cc[10], cc[11],   al0, al1, al2, al3, bh20, bh21);
                MMA16816(cc[12], cc[13], cc[14], cc[15], al0, al1, al2, al3, bh30, bh31);
                // t2: Ah*Bl
                MMA16816(cc[0], cc[1], cc[2], cc[3],     ah0, ah1, ah2, ah3, bl00, bl01);
                MMA16816(cc[4], cc[5], cc[6], cc[7],     ah0, ah1, ah2, ah3, bl10, bl11);
                MMA16816(cc[8], cc[9], cc[10], cc[11],   ah0, ah1, ah2, ah3, bl20, bl21);
                MMA16816(cc[12], cc[13], cc[14], cc[15], ah0, ah1, ah2, ah3, bl30, bl31);
            }
        }
        if (p + 1 < 4) {
            char* nbuf = abufs + ((p + 1) & 1) * ABUF_BYTES;
            int nrows = (p + 1 < 3) ? 64 : 16;
            conv_tile(nbuf, kbase, (p + 1) * 64, nrows, tid);
        }
        __syncthreads();
    }

    // ---- epilogue: C + bias -> prelu -> Ht[h][s] (overlay A bufs) ----
    float* Ht = sm;    // [64][SPAD]
    #pragma unroll
    for (int p = 0; p < 4; p++) {
        const bool active = (p < 3) || (wid < 2);
        if (active) {
            const int mt = (p < 3) ? (wid >> 1) : 0;
            const int nb = (p < 3) ? ((wid & 1) * 32) : (wid * 32);
            int srow = p * 64 + mt * 16 + (lid >> 2);
            #pragma unroll
            for (int j = 0; j < 4; j++) {
                int h = nb + 8 * j + (lid & 3) * 2;
                float2 bb = *reinterpret_cast<const float2*>(bias1 + h);
                float v0 = c0[p][4 * j + 0] + bb.x;
                float v1 = c0[p][4 * j + 1] + bb.y;
                float v2 = c0[p][4 * j + 2] + bb.x;
                float v3 = c0[p][4 * j + 3] + bb.y;
                v0 = (v0 >= 0.f) ? v0 : a1 * v0;
                v1 = (v1 >= 0.f) ? v1 : a1 * v1;
                v2 = (v2 >= 0.f) ? v2 : a1 * v2;
                v3 = (v3 >= 0.f) ? v3 : a1 * v3;
                if (srow < SS) {
                    Ht[h * SPAD + srow]       = v0;
                    Ht[(h + 1) * SPAD + srow] = v1;
                }
                if (srow + 8 < SS) {
                    Ht[h * SPAD + srow + 8]       = v2;
                    Ht[(h + 1) * SPAD + srow + 8] = v3;
                }
            }
        }
    }
    __syncthreads();

    // ---- layers 2+3 per s ----
    if (tid < SS) {
        const int s = tid;
        ull acc2[16];
        {
            const ulonglong2* bp = reinterpret_cast<const ulonglong2*>(b2s);
            #pragma unroll
            for (int j = 0; j < 8; j++) { acc2[2*j] = bp[j].x; acc2[2*j+1] = bp[j].y; }
        }
        #pragma unroll 8
        for (int h = 0; h < H1; h++) {
            ull xx = pk2(Ht[h * SPAD + s]);
            const ulonglong2* wr = reinterpret_cast<const ulonglong2*>(w2s + h * H2);
            #pragma unroll
            for (int j4 = 0; j4 < 8; j4++) {
                ulonglong2 wv = wr[j4];
                fma2(acc2[2*j4],   xx, wv.x);
                fma2(acc2[2*j4+1], xx, wv.y);
            }
        }
        float sc = b3;
        #pragma unroll
        for (int j = 0; j < 16; j++) {
            float2 p2 = up2(acc2[j]);
            float v0 = (p2.x >= 0.f) ? p2.x : a2 * p2.x;
            float v1 = (p2.y >= 0.f) ? p2.y : a2 * p2.y;
            sc = fmaf(v0, w3s[2*j], sc);
            sc = fmaf(v1, w3s[2*j + 1], sc);
        }
        int mv = kmask[(size_t)b * SS + s];
        score[s] = mv ? sc : -INFINITY;
    }
    __syncthreads();

    // ---- softmax via warp shuffles ----
    const float myscore = score[tid];
    float v = myscore;
    #pragma unroll
    for (int off = 16; off > 0; off >>= 1)
        v = fmaxf(v, __shfl_xor_sync(0xffffffffu, v, off));
    if (lid == 0) red[wid] = v;
    __syncthreads();
    if (tid < 32) {
        float mv = (tid < 8) ? red[tid] : -INFINITY;
        #pragma unroll
        for (int off = 4; off > 0; off >>= 1)
            mv = fmaxf(mv, __shfl_xor_sync(0xffffffffu, mv, off));
        if (tid == 0) red[32] = mv;
    }
    __syncthreads();
    const float m = red[32];

    float e = 0.f;
    if (tid < SS && m > -INFINITY && myscore > -INFINITY)
        e = expf(myscore - m);
    float es = e;
    #pragma unroll
    for (int off = 16; off > 0; off >>= 1)
        es += __shfl_xor_sync(0xffffffffu, es, off);
    if (lid == 0) red[wid] = es;
    __syncthreads();
    if (tid < 32) {
        float sv = (tid < 8) ? red[tid] : 0.f;
        #pragma unroll
        for (int off = 4; off > 0; off >>= 1)
            sv += __shfl_xor_sync(0xffffffffu, sv, off);
        if (tid == 0) red[32] = (sv > 0.f) ? (1.f / sv) : 0.f;
    }
    __syncthreads();
    const float inv = red[32];

    {
        float wv = e * inv;
        wgt[tid] = wv;
        if (tid < SS) out[(size_t)BB * DD + (size_t)b * SS + tid] = wv;
    }
    __syncthreads();

    // ---- weighted sum: out[b,d] = sum_s wgt[s]*keys[b,s,d] ----
    if (tid < DD) {
        const float* kb = kbase + tid;
        float accw = 0.f;
        #pragma unroll 8
        for (int si = 0; si < SS; si++)
            accw = fmaf(wgt[si], kb[(size_t)si * DD], accw);
        out[(size_t)b * DD + tid] = accw;
    }
}

extern "C" void kernel_launch(void* const* d_in, const int* in_sizes, int n_in,
                              void* d_out, int out_size)
{
    const float* query = (const float*)d_in[0];
    const float* keys  = (const float*)d_in[1];
    const int*   mask  = (const int*)  d_in[2];
    const float* W1    = (const float*)d_in[3];
    const float* b1    = (const float*)d_in[4];
    const float* a1    = (const float*)d_in[5];
    const float* W2    = (const float*)d_in[6];
    const float* b2    = (const float*)d_in[7];
    const float* a2    = (const float*)d_in[8];
    const float* W3    = (const float*)d_in[9];
    const float* b3    = (const float*)d_in[10];
    float* out = (float*)d_out;

    static bool attr_set = false;
    if (!attr_set) {
        cudaFuncSetAttribute(rich_attn_kernel,
                             cudaFuncAttributeMaxDynamicSharedMemorySize,
                             SMEM_FLOATS * sizeof(float));
        attr_set = true;
    }

    rich_attn_kernel<<<BB, NT, SMEM_FLOATS * sizeof(float)>>>(
        query, keys, mask, W1, b1, a1, W2, b2, a2, W3, b3, out);
}

// round 11
// speedup vs baseline: 1.7323x; 1.7323x over previous
#include <cuda_runtime.h>
#include <cuda_bf16.h>
#include <math.h>
#include <stdint.h>

#define BB 2048
#define SS 200
#define DD 192
#define H1 64
#define H2 32
#define NT 256
#define SPAD 208

typedef unsigned long long ull;

// ---- smem layout (float idx) ----
#define SM_AB 0                        // A buf: 64row * 768B = 49152 B = 12288 f (Ht overlay after GEMM)
#define SM_B  12288                    // B [64][384] bf16 hi/lo = 49152 B = 12288 f
#define SM_QS 24576                    // 192
#define SM_B1 (SM_QS + 192)            // 64
#define SM_W2 (SM_B1 + 64)             // 2048
#define SM_W3 (SM_W2 + 2048)           // 32
#define SM_B2 (SM_W3 + 32)             // 32
#define SM_SC (SM_B2 + 32)             // 256
#define SM_WGT (SM_SC + 256)           // 256
#define SM_RED (SM_WGT + 256)          // 64
#define SMEM_FLOATS (SM_RED + 64)      // 27520 f = 110080 B -> 2 CTAs/SM

static __device__ __forceinline__ ull pk2(float x) {
    ull r; asm("mov.b64 %0, {%1, %1};" : "=l"(r) : "f"(x)); return r;
}
static __device__ __forceinline__ void fma2(ull& d, ull a, ull b) {
    asm("fma.rn.f32x2 %0, %1, %2, %0;" : "+l"(d) : "l"(a), "l"(b));
}
static __device__ __forceinline__ float2 up2(ull v) {
    float2 r; asm("mov.b64 {%0, %1}, %2;" : "=f"(r.x), "=f"(r.y) : "l"(v)); return r;
}

#define LDSM4(r0, r1, r2, r3, addr) \
    asm volatile("ldmatrix.sync.aligned.m8n8.x4.shared.b16 {%0,%1,%2,%3}, [%4];" \
                 : "=r"(r0), "=r"(r1), "=r"(r2), "=r"(r3) : "r"(addr))

#define MMA16816(d0, d1, d2, d3, a0, a1, a2, a3, b0, b1) \
    asm volatile("mma.sync.aligned.m16n8k16.row.col.f32.bf16.bf16.f32 " \
                 "{%0,%1,%2,%3},{%4,%5,%6,%7},{%8,%9},{%0,%1,%2,%3};" \
                 : "+f"(d0), "+f"(d1), "+f"(d2), "+f"(d3) \
                 : "r"(a0), "r"(a1), "r"(a2), "r"(a3), "r"(b0), "r"(b1))

// Convert one 64-row A tile (keys rows [row0,row0+nrows)) to bf16 hi/lo, swizzled.
static __device__ __forceinline__ void conv_tile(char* abuf, const float* kbase, int row0, int nrows, int tid) {
    int total = nrows * 48;            // float4 units
    for (int f = tid; f < total; f += NT) {
        int r = f / 48;
        int q = f - r * 48;
        int grow = row0 + r;
        float4 kv = make_float4(0.f, 0.f, 0.f, 0.f);
        if (grow < SS)
            kv = *reinterpret_cast<const float4*>(kbase + (size_t)grow * DD + 4 * q);
        __nv_bfloat162 h01 = __floats2bfloat162_rn(kv.x, kv.y);
        __nv_bfloat162 h23 = __floats2bfloat162_rn(kv.z, kv.w);
        __nv_bfloat162 l01 = __floats2bfloat162_rn(kv.x - __bfloat162float(h01.x),
                                                   kv.y - __bfloat162float(h01.y));
        __nv_bfloat162 l23 = __floats2bfloat162_rn(kv.z - __bfloat162float(h23.x),
                                                   kv.w - __bfloat162float(h23.y));
        uint32_t x   = (uint32_t)(r & 7) << 4;
        uint32_t rb  = (uint32_t)r * 768u;
        uint32_t cbh = ((uint32_t)(8 * q)) ^ x;          // hi bytes
        uint32_t cbl = ((uint32_t)(384 + 8 * q)) ^ x;    // lo bytes
        uint2 hv, lv;
        hv.x = *reinterpret_cast<uint32_t*>(&h01);
        hv.y = *reinterpret_cast<uint32_t*>(&h23);
        lv.x = *reinterpret_cast<uint32_t*>(&l01);
        lv.y = *reinterpret_cast<uint32_t*>(&l23);
        *reinterpret_cast<uint2*>(abuf + rb + cbh) = hv;
        *reinterpret_cast<uint2*>(abuf + rb + cbl) = lv;
    }
}

__global__ __launch_bounds__(NT, 2)
void rich_attn_kernel(const float* __restrict__ query,
                      const float* __restrict__ keys,
                      const int*   __restrict__ kmask,
                      const float* __restrict__ W1,
                      const float* __restrict__ b1,
                      const float* __restrict__ a1p,
                      const float* __restrict__ W2,
                      const float* __restrict__ b2,
                      const float* __restrict__ a2p,
                      const float* __restrict__ W3,
                      const float* __restrict__ b3p,
                      float* __restrict__ out)
{
    extern __shared__ float sm[];
    const int tid = threadIdx.x;
    const int wid = tid >> 5;
    const int lid = tid & 31;
    const int b   = blockIdx.x;

    const float a1 = a1p[0];
    const float a2 = a2p[0];
    const float b3 = b3p[0];

    const float* kbase = keys + (size_t)b * SS * DD;
    char* abuf = reinterpret_cast<char*>(sm + SM_AB);
    char* smB  = reinterpret_cast<char*>(sm + SM_B);
    const uint32_t base_u32 = (uint32_t)__cvta_generic_to_shared((void*)sm);
    const uint32_t abase_u32 = base_u32;                 // SM_AB = 0
    const uint32_t bbase_u32 = base_u32 + SM_B * 4;

    float* qs    = sm + SM_QS;
    float* bias1 = sm + SM_B1;
    float* w2s   = sm + SM_W2;
    float* w3s   = sm + SM_W3;
    float* b2s   = sm + SM_B2;
    float* score = sm + SM_SC;
    float* wgt   = sm + SM_WGT;
    float* red   = sm + SM_RED;

    // ---- small loads ----
    if (tid < DD) qs[tid] = query[(size_t)b * DD + tid];
    for (int idx = tid; idx < H1 * H2; idx += NT) w2s[idx] = W2[idx];
    if (tid < H2) { w3s[tid] = W3[tid]; b2s[tid] = b2[tid]; }
    if (tid >= SS) score[tid] = -INFINITY;
    __syncthreads();   // qs ready

    // ---- B = weffT hi/lo, swizzled [h][384] ----
    for (int idx = tid; idx < DD * H1; idx += NT) {
        int k = idx >> 6;
        int h = idx & 63;
        float v = W1[idx] + W1[(size_t)(576 + k) * H1 + h] + qs[k] * W1[(size_t)(384 + k) * H1 + h];
        __nv_bfloat16 hb = __float2bfloat16_rn(v);
        __nv_bfloat16 lb = __float2bfloat16_rn(v - __bfloat162float(hb));
        uint32_t x  = (uint32_t)(h & 7) << 4;
        uint32_t rb = (uint32_t)h * 768u;
        *reinterpret_cast<__nv_bfloat16*>(smB + rb + (((uint32_t)(2 * k)) ^ x))       = hb;
        *reinterpret_cast<__nv_bfloat16*>(smB + rb + (((uint32_t)(384 + 2 * k)) ^ x)) = lb;
    }
    // ---- bias1 partials (wgt scratch) ----
    {
        int h = tid & 63;
        int c = tid >> 6;
        float acc_ = 0.f;
        int i0 = c * 48;
        #pragma unroll 4
        for (int i = i0; i < i0 + 48; i++)
            acc_ = fmaf(qs[i], W1[(size_t)(192 + i) * H1 + h] - W1[(size_t)(576 + i) * H1 + h], acc_);
        wgt[tid] = acc_;
    }
    // ---- conv pass 0 -> A buf ----
    conv_tile(abuf, kbase, 0, 64, tid);
    __syncthreads();
    if (tid < H1)
        bias1[tid] = b1[tid] + wgt[tid] + wgt[tid + 64] + wgt[tid + 128] + wgt[tid + 192];

    // ---- GEMM passes (single A buffer: gemm p, sync, conv p+1, sync) ----
    float c0[4][16];        // [pass][4 n8-tiles * 4]
    #pragma unroll
    for (int p = 0; p < 4; p++)
        #pragma unroll
        for (int j = 0; j < 16; j++) c0[p][j] = 0.f;

    const uint32_t uA = ((uint32_t)(lid >> 4)) * 16u;
    const uint32_t jB = (uint32_t)(lid >> 3);
    const uint32_t uB = (jB & 1u) * 16u;
    const uint32_t xb = ((uint32_t)(lid & 7)) << 4;

    for (int p = 0; p < 4; p++) {
        const bool active = (p < 3) || (wid < 2);
        if (active) {
            const int mt = (p < 3) ? (wid >> 1) : 0;
            const int nb = (p < 3) ? ((wid & 1) * 32) : (wid * 32);
            const uint32_t rowA = (uint32_t)(mt * 16 + (lid & 15));
            const uint32_t xa = (rowA & 7u) << 4;
            const uint32_t aB = abase_u32 + rowA * 768u;
            const uint32_t rowB0 = (uint32_t)nb + (jB >> 1) * 8u + (uint32_t)(lid & 7);
            const uint32_t bB0 = bbase_u32 + rowB0 * 768u;
            const uint32_t bB1 = bB0 + 16u * 768u;
            float* cc = c0[p];

            #pragma unroll
            for (int ks = 0; ks < 12; ks++) {
                uint32_t kh = (uint32_t)(ks * 32);
                uint32_t kl = kh + 384u;
                uint32_t ah0, ah1, ah2, ah3, al0, al1, al2, al3;
                LDSM4(ah0, ah1, ah2, ah3, aB + ((kh + uA) ^ xa));
                LDSM4(al0, al1, al2, al3, aB + ((kl + uA) ^ xa));
                uint32_t bh00, bh01, bh10, bh11, bh20, bh21, bh30, bh31;
                LDSM4(bh00, bh01, bh10, bh11, bB0 + ((kh + uB) ^ xb));
                LDSM4(bh20, bh21, bh30, bh31, bB1 + ((kh + uB) ^ xb));
                uint32_t bl00, bl01, bl10, bl11, bl20, bl21, bl30, bl31;
                LDSM4(bl00, bl01, bl10, bl11, bB0 + ((kl + uB) ^ xb));
                LDSM4(bl20, bl21, bl30, bl31, bB1 + ((kl + uB) ^ xb));

                MMA16816(cc[0], cc[1], cc[2], cc[3],     ah0, ah1, ah2, ah3, bh00, bh01);
                MMA16816(cc[4], cc[5], cc[6], cc[7],     ah0, ah1, ah2, ah3, bh10, bh11);
                MMA16816(cc[8], cc[9], cc[10], cc[11],   ah0, ah1, ah2, ah3, bh20, bh21);
                MMA16816(cc[12], cc[13], cc[14], cc[15], ah0, ah1, ah2, ah3, bh30, bh31);

                MMA16816(cc[0], cc[1], cc[2], cc[3],     al0, al1, al2, al3, bh00, bh01);
                MMA16816(cc[4], cc[5], cc[6], cc[7],     al0, al1, al2, al3, bh10, bh11);
                MMA16816(cc[8], cc[9], cc[10], cc[11],   al0, al1, al2, al3, bh20, bh21);
                MMA16816(cc[12], cc[13], cc[14], cc[15], al0, al1, al2, al3, bh30, bh31);

                MMA16816(cc[0], cc[1], cc[2], cc[3],     ah0, ah1, ah2, ah3, bl00, bl01);
                MMA16816(cc[4], cc[5], cc[6], cc[7],     ah0, ah1, ah2, ah3, bl10, bl11);
                MMA16816(cc[8], cc[9], cc[10], cc[11],   ah0, ah1, ah2, ah3, bl20, bl21);
                MMA16816(cc[12], cc[13], cc[14], cc[15], ah0, ah1, ah2, ah3, bl30, bl31);
            }
        }
        __syncthreads();   // all warps done reading A buf for pass p
        if (p + 1 < 4) {
            int nrows = (p + 1 < 3) ? 64 : 16;
            conv_tile(abuf, kbase, (p + 1) * 64, nrows, tid);
            __syncthreads();   // next pass data ready
        }
    }

    // ---- epilogue: C + bias -> prelu -> Ht[h][s] (overlay A + B head) ----
    float* Ht = sm;    // [64][SPAD] = 13312 f < 24576
    #pragma unroll
    for (int p = 0; p < 4; p++) {
        const bool active = (p < 3) || (wid < 2);
        if (active) {
            const int mt = (p < 3) ? (wid >> 1) : 0;
            const int nb = (p < 3) ? ((wid & 1) * 32) : (wid * 32);
            int srow = p * 64 + mt * 16 + (lid >> 2);
            #pragma unroll
            for (int j = 0; j < 4; j++) {
                int h = nb + 8 * j + (lid & 3) * 2;
                float2 bb = *reinterpret_cast<const float2*>(bias1 + h);
                float v0 = c0[p][4 * j + 0] + bb.x;
                float v1 = c0[p][4 * j + 1] + bb.y;
                float v2 = c0[p][4 * j + 2] + bb.x;
                float v3 = c0[p][4 * j + 3] + bb.y;
                v0 = (v0 >= 0.f) ? v0 : a1 * v0;
                v1 = (v1 >= 0.f) ? v1 : a1 * v1;
                v2 = (v2 >= 0.f) ? v2 : a1 * v2;
                v3 = (v3 >= 0.f) ? v3 : a1 * v3;
                if (srow < SS) {
                    Ht[h * SPAD + srow]       = v0;
                    Ht[(h + 1) * SPAD + srow] = v1;
                }
                if (srow + 8 < SS) {
                    Ht[h * SPAD + srow + 8]       = v2;
                    Ht[(h + 1) * SPAD + srow + 8] = v3;
                }
            }
        }
    }
    __syncthreads();

    // ---- layers 2+3 per s ----
    if (tid < SS) {
        const int s = tid;
        ull acc2[16];
        {
            const ulonglong2* bp = reinterpret_cast<const ulonglong2*>(b2s);
            #pragma unroll
            for (int j = 0; j < 8; j++) { acc2[2*j] = bp[j].x; acc2[2*j+1] = bp[j].y; }
        }
        #pragma unroll 8
        for (int h = 0; h < H1; h++) {
            ull xx = pk2(Ht[h * SPAD + s]);
            const ulonglong2* wr = reinterpret_cast<const ulonglong2*>(w2s + h * H2);
            #pragma unroll
            for (int j4 = 0; j4 < 8; j4++) {
                ulonglong2 wv = wr[j4];
                fma2(acc2[2*j4],   xx, wv.x);
                fma2(acc2[2*j4+1], xx, wv.y);
            }
        }
        float sc = b3;
        #pragma unroll
        for (int j = 0; j < 16; j++) {
            float2 p2 = up2(acc2[j]);
            float v0 = (p2.x >= 0.f) ? p2.x : a2 * p2.x;
            float v1 = (p2.y >= 0.f) ? p2.y : a2 * p2.y;
            sc = fmaf(v0, w3s[2*j], sc);
            sc = fmaf(v1, w3s[2*j + 1], sc);
        }
        int mv = kmask[(size_t)b * SS + s];
        score[s] = mv ? sc : -INFINITY;
    }
    __syncthreads();

    // ---- softmax via warp shuffles ----
    const float myscore = score[tid];
    float v = myscore;
    #pragma unroll
    for (int off = 16; off > 0; off >>= 1)
        v = fmaxf(v, __shfl_xor_sync(0xffffffffu, v, off));
    if (lid == 0) red[wid] = v;
    __syncthreads();
    if (tid < 32) {
        float mv = (tid < 8) ? red[tid] : -INFINITY;
        #pragma unroll
        for (int off = 4; off > 0; off >>= 1)
            mv = fmaxf(mv, __shfl_xor_sync(0xffffffffu, mv, off));
        if (tid == 0) red[32] = mv;
    }
    __syncthreads();
    const float m = red[32];

    float e = 0.f;
    if (tid < SS && m > -INFINITY && myscore > -INFINITY)
        e = expf(myscore - m);
    float es = e;
    #pragma unroll
    for (int off = 16; off > 0; off >>= 1)
        es += __shfl_xor_sync(0xffffffffu, es, off);
    if (lid == 0) red[wid] = es;
    __syncthreads();
    if (tid < 32) {
        float sv = (tid < 8) ? red[tid] : 0.f;
        #pragma unroll
        for (int off = 4; off > 0; off >>= 1)
            sv += __shfl_xor_sync(0xffffffffu, sv, off);
        if (tid == 0) red[32] = (sv > 0.f) ? (1.f / sv) : 0.f;
    }
    __syncthreads();
    const float inv = red[32];

    {
        float wv = e * inv;
        wgt[tid] = wv;
        if (tid < SS) out[(size_t)BB * DD + (size_t)b * SS + tid] = wv;
    }
    __syncthreads();

    // ---- weighted sum: out[b,d] = sum_s wgt[s]*keys[b,s,d] ----
    if (tid < DD) {
        const float* kb = kbase + tid;
        float accw = 0.f;
        #pragma unroll 8
        for (int si = 0; si < SS; si++)
            accw = fmaf(wgt[si], kb[(size_t)si * DD], accw);
        out[(size_t)b * DD + tid] = accw;
    }
}

extern "C" void kernel_launch(void* const* d_in, const int* in_sizes, int n_in,
                              void* d_out, int out_size)
{
    const float* query = (const float*)d_in[0];
    const float* keys  = (const float*)d_in[1];
    const int*   mask  = (const int*)  d_in[2];
    const float* W1    = (const float*)d_in[3];
    const float* b1    = (const float*)d_in[4];
    const float* a1    = (const float*)d_in[5];
    const float* W2    = (const float*)d_in[6];
    const float* b2    = (const float*)d_in[7];
    const float* a2    = (const float*)d_in[8];
    const float* W3    = (const float*)d_in[9];
    const float* b3    = (const float*)d_in[10];
    float* out = (float*)d_out;

    static bool attr_set = false;
    if (!attr_set) {
        cudaFuncSetAttribute(rich_attn_kernel,
                             cudaFuncAttributeMaxDynamicSharedMemorySize,
                             SMEM_FLOATS * sizeof(float));
        attr_set = true;
    }

    rich_attn_kernel<<<BB, NT, SMEM_FLOATS * sizeof(float)>>>(
        query, keys, mask, W1, b1, a1, W2, b2, a2, W3, b3, out);
}